// round 14
// baseline (speedup 1.0000x reference)
#include <cuda_runtime.h>
#include <cuda_fp16.h>
#include <cstdint>

// Problem constants (fixed per reference)
#define Bn 8
#define Hn 1080
#define Wn 1920
constexpr int HW   = Hn * Wn;          // 2,073,600
constexpr int BHW  = Bn * HW;          // 16,588,800
constexpr int WP   = Wn / 2;           // 960 pair-cells per row
constexpr int LAT1 = Hn * WP;          // 1,036,800 pair-cells per parity lattice
constexpr int SLOT = 2 * LAT1;         // cells per slot (both parities)

// THREE-SLOT rotating pair-cell lattices. Slot s = [parity0 | parity1].
// 16B cell = [vx0,vy0,w0,pad | vx1,vy1,w1,pad] (8 x f16)   [R6 layout]
// Parity 0 (even): pair k covers corners (2k, 2k+1)
// Parity 1 (odd):  pair k covers corners (2k+1, 2k+2)
// Every slot is explicitly zeroed before every splat into it (replay-safe).
__device__ float4        g_lat[3 * SLOT];   // 99.6 MB (three slots)
__device__ unsigned char g_mask[BHW];       // count>0 flag (whole image)
__device__ int           g_holes[BHW];      // compacted hole indices
__device__ int           g_hole_count;

// Block-role interleave for the slice kernel: per 7-block group,
// 2 splat blocks : 1 norm block : 4 zero blocks  (4050 : 2025 : 8100)
constexpr int GROUPS       = 2025;
constexpr int SLICE_BLOCKS = GROUPS * 7;    // 14175

// --- bit reinterpretation helpers (header-portable) ------------------------
__device__ __forceinline__ unsigned h2_to_u32(__half2 h) {
    union { __half2 h; unsigned u; } cvt; cvt.h = h; return cvt.u;
}
__device__ __forceinline__ __half2 u32_to_h2(unsigned u) {
    union { unsigned u; __half2 h; } cvt; cvt.u = u; return cvt.h;
}

// One 16B vectorized f16x2 reduction: deposits (vx,vy,w) to TWO adjacent corners.
__device__ __forceinline__ void red_add_v4_f16x2(float4* p, unsigned r0, unsigned r1,
                                                 unsigned r2, unsigned r3) {
    asm volatile("red.global.add.noftz.v4.f16x2 [%0], {%1, %2, %3, %4};"
                 :: "l"(p), "r"(r0), "r"(r1), "r"(r2), "r"(r3) : "memory");
}

// ---------------------------------------------------------------------------
// Prologue: zero slot 0 + reset hole counter.
// ---------------------------------------------------------------------------
__global__ void zero_kernel(int slot, int reset_counter) {
    int i = blockIdx.x * blockDim.x + threadIdx.x;
    g_lat[(size_t)slot * SLOT + i] = make_float4(0.f, 0.f, 0.f, 0.f);
    if (reset_counter && i == 0) g_hole_count = 0;
}

// ---------------------------------------------------------------------------
// Splat body: two pixels per thread (proven R10 form).
// ---------------------------------------------------------------------------
__device__ __forceinline__ void splat_one(float4* slotBase, int x, int y,
                                          float fx, float fy, float w) {
    const float x2 = (float)x + fx;
    const float y2 = (float)y + fy;

    // Invalid pixels deposit exactly 0 in the reference -> skip.
    if (!(x2 >= 0.0f && x2 <= (float)(Wn - 1) &&
          y2 >= 0.0f && y2 <= (float)(Hn - 1)))
        return;

    const float vx = -fx * w;
    const float vy = -fy * w;

    // floor == trunc (non-negative by validity check)
    const int ixL = (int)x2;
    const int iyT = (int)y2;
    const int ixR = min(ixL + 1, Wn - 1);
    const int iyB = min(iyT + 1, Hn - 1);

    // lo half -> corner ixL, hi half -> corner ixR.
    // ixR==ixL (x2 == W-1 exactly): double lo payload, zero hi
    // (rn(2v) == 2*rn(v) in f16, bit-identical to two adds).
    const bool  dup = (ixR == ixL);
    const float m   = dup ? 2.0f : 1.0f;

    const unsigned r0 = h2_to_u32(__floats2half2_rn(vx * m, vy * m));
    const unsigned r1 = h2_to_u32(__floats2half2_rn(w * m, 0.0f));
    const unsigned r2 = dup ? 0u : h2_to_u32(__floats2half2_rn(vx, vy));
    const unsigned r3 = dup ? 0u : h2_to_u32(__floats2half2_rn(w, 0.0f));

    const int s  = ixL & 1;        // lattice parity
    const int kp = ixL >> 1;       // pair index

    float4* lat = slotBase + (size_t)s * LAT1 + kp;
    red_add_v4_f16x2(lat + iyT * WP, r0, r1, r2, r3);
    red_add_v4_f16x2(lat + iyB * WP, r0, r1, r2, r3);
}

__device__ __forceinline__ void splat_body(int t, const float* __restrict__ flow,
                                           const float* __restrict__ depth,
                                           float4* slotBase) {
    const int p2 = t * 2;
    const int y  = p2 / Wn;
    const int x  = p2 - y * Wn;

    const float2 fx01 = *(const float2*)(flow + p2);
    const float2 fy01 = *(const float2*)(flow + HW + p2);
    const float2 d01  = *(const float2*)(depth + p2);

    splat_one(slotBase, x,     y, fx01.x, fy01.x, d01.x);
    splat_one(slotBase, x + 1, y, fx01.y, fy01.y, d01.y);
}

// ---------------------------------------------------------------------------
// Normalize body (4 pixels/thread, R12-proven). latS = slot base.
// ---------------------------------------------------------------------------
__device__ __forceinline__ void normalize_body(int t, const float4* latS,
                                               float* __restrict__ out, int gbase) {
    const int p4 = t * 4;
    const int y  = p4 / Wn;
    const int x0 = p4 - y * Wn;       // multiple of 4
    const int k  = x0 >> 1;           // even-lattice pair index (even)

    const size_t rowc = (size_t)y * WP;
    const uint4* latE = (const uint4*)latS;
    const uint2* latO = (const uint2*)(latS + (size_t)LAT1);   // 8B half-cells

    const uint4 e0 = latE[rowc + k];
    const uint4 e1 = latE[rowc + k + 1];

    float2 xyO0 = make_float2(0.f, 0.f);
    float  wO0  = 0.f;
    if (x0 > 0) {
        const uint2 oh = latO[((rowc + k - 1) << 1) | 1];   // odd pair k-1 hi
        xyO0 = __half22float2(u32_to_h2(oh.x));
        wO0  = __low2float(u32_to_h2(oh.y));
    }
    const uint4 om = latE[(size_t)LAT1 + rowc + k];          // odd pair k full
    const uint2 ol = latO[((rowc + k + 1) << 1)];            // odd pair k+1 lo

    float sxv[4], syv[4], cntv[4];
    {
        const float2 xyE = __half22float2(u32_to_h2(e0.x));
        const float  wE  = __low2float(u32_to_h2(e0.y));
        sxv[0] = xyE.x + xyO0.x; syv[0] = xyE.y + xyO0.y; cntv[0] = wE + wO0;
    }
    {
        const float2 xyE = __half22float2(u32_to_h2(e0.z));
        const float  wE  = __low2float(u32_to_h2(e0.w));
        const float2 xyO = __half22float2(u32_to_h2(om.x));
        const float  wO  = __low2float(u32_to_h2(om.y));
        sxv[1] = xyE.x + xyO.x; syv[1] = xyE.y + xyO.y; cntv[1] = wE + wO;
    }
    {
        const float2 xyE = __half22float2(u32_to_h2(e1.x));
        const float  wE  = __low2float(u32_to_h2(e1.y));
        const float2 xyO = __half22float2(u32_to_h2(om.z));
        const float  wO  = __low2float(u32_to_h2(om.w));
        sxv[2] = xyE.x + xyO.x; syv[2] = xyE.y + xyO.y; cntv[2] = wE + wO;
    }
    {
        const float2 xyE = __half22float2(u32_to_h2(e1.z));
        const float  wE  = __low2float(u32_to_h2(e1.w));
        const float2 xyO = __half22float2(u32_to_h2(ol.x));
        const float  wO  = __low2float(u32_to_h2(ol.y));
        sxv[3] = xyE.x + xyO.x; syv[3] = xyE.y + xyO.y; cntv[3] = wE + wO;
    }

    bool  h[4];
    float ox[4], oy[4];
    unsigned maskw = 0;
#pragma unroll
    for (int j = 0; j < 4; ++j) {
        h[j] = !(cntv[j] > 0.0f);
        const float inv = 1.0f / (h[j] ? 1.0f : cntv[j]);
        ox[j] = sxv[j] * inv;
        oy[j] = syv[j] * inv;
        maskw |= (h[j] ? 0u : 1u) << (j * 8);
    }

    *(float4*)(out + p4)      = make_float4(ox[0], ox[1], ox[2], ox[3]);
    *(float4*)(out + HW + p4) = make_float4(oy[0], oy[1], oy[2], oy[3]);
    *(unsigned*)(g_mask + gbase + p4) = maskw;

    const unsigned b0 = __ballot_sync(0xffffffffu, h[0]);
    const unsigned b1 = __ballot_sync(0xffffffffu, h[1]);
    const unsigned b2 = __ballot_sync(0xffffffffu, h[2]);
    const unsigned b3 = __ballot_sync(0xffffffffu, h[3]);
    const unsigned any = b0 | b1 | b2 | b3;
    if (any) {
        const int lane   = threadIdx.x & 31;
        const int leader = __ffs(any) - 1;
        const int total  = __popc(b0) + __popc(b1) + __popc(b2) + __popc(b3);
        int base = 0;
        if (lane == leader) base = atomicAdd(&g_hole_count, total);
        base = __shfl_sync(0xffffffffu, base, leader);
        const unsigned below = (1u << lane) - 1u;
        int off = base;
        if (h[0]) g_holes[off + __popc(b0 & below)] = gbase + p4;
        off += __popc(b0);
        if (h[1]) g_holes[off + __popc(b1 & below)] = gbase + p4 + 1;
        off += __popc(b1);
        if (h[2]) g_holes[off + __popc(b2 & below)] = gbase + p4 + 2;
        off += __popc(b2);
        if (h[3]) g_holes[off + __popc(b3 & below)] = gbase + p4 + 3;
    }
}

// ---------------------------------------------------------------------------
// Slice kernel: interleaved block roles (2 splat : 1 norm : 4 zero per group).
//   splat slice b  -> slot sSplat
//   norm  slice b-1 <- slot sNorm   (if doNorm)
//   zero  slot sZero for slice b+1  (if doZero)
// Slots pairwise distinct (mod-3 rotation) -> race-free.
// ---------------------------------------------------------------------------
__global__ void slice_kernel(const float* __restrict__ flow,
                             const float* __restrict__ depth,
                             float* __restrict__ outPrev, int gbasePrev,
                             int sSplat, int sNorm, int sZero,
                             int doNorm, int doZero) {
    const int group = blockIdx.x / 7;
    const int r     = blockIdx.x - group * 7;

    if (r < 2) {
        // splat block
        const int t = (group * 2 + r) * blockDim.x + threadIdx.x;   // [0, HW/2)
        splat_body(t, flow, depth, g_lat + (size_t)sSplat * SLOT);
    } else if (r == 2) {
        // normalize block
        if (doNorm) {
            const int t = group * blockDim.x + threadIdx.x;         // [0, HW/4)
            normalize_body(t, g_lat + (size_t)sNorm * SLOT, outPrev, gbasePrev);
        }
    } else {
        // zero block
        if (doZero) {
            const int i = (group * 4 + (r - 3)) * blockDim.x + threadIdx.x;  // [0, HW)
            g_lat[(size_t)sZero * SLOT + i] = make_float4(0.f, 0.f, 0.f, 0.f);
        }
    }
}

// Normalize-only kernel (final slice drain).
__global__ void norm_kernel(float* __restrict__ out, int gbase, int slot) {
    normalize_body(blockIdx.x * blockDim.x + threadIdx.x,
                   g_lat + (size_t)slot * SLOT, out, gbase);
}

// ---------------------------------------------------------------------------
// Hole fill over the compacted list (~2% of pixels).
// ---------------------------------------------------------------------------
__global__ void fill_kernel(float* __restrict__ out) {
    const int n      = g_hole_count;
    const int stride = gridDim.x * blockDim.x;

    for (int j = blockIdx.x * blockDim.x + threadIdx.x; j < n; j += stride) {
        const int i = g_holes[j];
        const int b = i / HW;
        const int p = i - b * HW;
        const int y = p / Wn;
        const int x = p - y * Wn;

        const unsigned char* m  = g_mask + (size_t)b * HW;
        float*               o0 = out + (size_t)b * 2 * HW;
        float*               o1 = o0 + HW;

        float sx = 0.f, sy = 0.f;
        int   s  = 0;

        for (int xx = x - 1; xx >= 0; --xx) {            // left
            int q = y * Wn + xx;
            if (m[q]) { sx += o0[q]; sy += o1[q]; s++; break; }
        }
        for (int xx = x + 1; xx < Wn; ++xx) {            // right
            int q = y * Wn + xx;
            if (m[q]) { sx += o0[q]; sy += o1[q]; s++; break; }
        }
        for (int yy = y - 1; yy >= 0; --yy) {            // up
            int q = yy * Wn + x;
            if (m[q]) { sx += o0[q]; sy += o1[q]; s++; break; }
        }
        for (int yy = y + 1; yy < Hn; ++yy) {            // down
            int q = yy * Wn + x;
            if (m[q]) { sx += o0[q]; sy += o1[q]; s++; break; }
        }

        if (s > 0) {
            const float inv = 1.0f / (float)s;
            o0[y * Wn + x] = sx * inv;
            o1[y * Wn + x] = sy * inv;
        }
        // s == 0: out already 0 at holes (count==0 implies acc.xy==0)
    }
}

// ---------------------------------------------------------------------------
// Launch: 3-slot rotating pipeline, one fully-overlapped kernel per slice.
// ---------------------------------------------------------------------------
extern "C" void kernel_launch(void* const* d_in, const int* in_sizes, int n_in,
                              void* d_out, int out_size) {
    const float* flow  = (const float*)d_in[0];   // (B, 2, H, W) fp32
    const float* depth = (const float*)d_in[1];   // (B, 1, H, W) fp32
    float*       out   = (float*)d_out;           // (B, 2, H, W) fp32

    zero_kernel<<<8100, 256>>>(0, 1);             // slot 0 + reset hole counter

    for (int b = 0; b < Bn; ++b) {
        slice_kernel<<<SLICE_BLOCKS, 256>>>(
            flow + (size_t)b * 2 * HW,
            depth + (size_t)b * HW,
            b > 0 ? out + (size_t)(b - 1) * 2 * HW : out,
            (b - 1) * HW,
            b % 3, (b - 1 + 3) % 3, (b + 1) % 3,
            /*doNorm=*/b > 0 ? 1 : 0,
            /*doZero=*/b < Bn - 1 ? 1 : 0);
    }
    norm_kernel<<<GROUPS, 256>>>(out + (size_t)(Bn - 1) * 2 * HW,
                                 (Bn - 1) * HW, (Bn - 1) % 3);
    fill_kernel<<<2048, 256>>>(out);
}

// round 15
// speedup vs baseline: 1.9109x; 1.9109x over previous
#include <cuda_runtime.h>
#include <cuda_fp16.h>
#include <cstdint>

// Problem constants (fixed per reference)
#define Bn 8
#define Hn 1080
#define Wn 1920
constexpr int HW   = Hn * Wn;          // 2,073,600
constexpr int BHW  = Bn * HW;          // 16,588,800
constexpr int WP   = Wn / 2;           // 960 pair-cells per row
constexpr int LAT1 = Hn * WP;          // 1,036,800 pair-cells per parity lattice

// PING-PONG pair-cell lattice slots (R13 proven). Slot s = [parity0 | parity1].
// 16B cell = [vx0,vy0,w0,pad | vx1,vy1,w1,pad] (8 x f16)
// Parity 0 (even): pair k covers corners (2k, 2k+1)
// Parity 1 (odd):  pair k covers corners (2k+1, 2k+2)
// Every slot is explicitly zeroed before every splat into it (replay-safe).
__device__ float4        g_lat[2 * 2 * LAT1];   // 66.4 MB (two slots)
__device__ unsigned char g_mask[BHW];           // count>0 flag (whole image)
__device__ int           g_holes[BHW];          // compacted hole indices
__device__ int           g_hole_count;

constexpr int NORM_BLOCKS = 2025;   // HW/4 threads @256
constexpr int ZERO_BLOCKS = 8100;   // HW cells  @256

// --- bit reinterpretation helpers (header-portable) ------------------------
__device__ __forceinline__ unsigned h2_to_u32(__half2 h) {
    union { __half2 h; unsigned u; } cvt; cvt.h = h; return cvt.u;
}
__device__ __forceinline__ __half2 u32_to_h2(unsigned u) {
    union { unsigned u; __half2 h; } cvt; cvt.u = u; return cvt.h;
}

// One 16B vectorized f16x2 reduction: deposits (vx,vy,w) to TWO adjacent corners.
__device__ __forceinline__ void red_add_v4_f16x2(float4* p, unsigned r0, unsigned r1,
                                                 unsigned r2, unsigned r3) {
    asm volatile("red.global.add.noftz.v4.f16x2 [%0], {%1, %2, %3, %4};"
                 :: "l"(p), "r"(r0), "r"(r1), "r"(r2), "r"(r3) : "memory");
}

// ---------------------------------------------------------------------------
// Zero one slot (1 float4/thread, proven coalesced form; restores L2 residency)
// ---------------------------------------------------------------------------
__global__ void zero_kernel(int slot, int reset_counter) {
    int i = blockIdx.x * blockDim.x + threadIdx.x;
    g_lat[(size_t)slot * 2 * LAT1 + i] = make_float4(0.f, 0.f, 0.f, 0.f);
    if (reset_counter && i == 0) g_hole_count = 0;
}

// ---------------------------------------------------------------------------
// Forward splat for ONE batch slice into slot, TWO pixels per thread.
// ---------------------------------------------------------------------------
__device__ __forceinline__ void splat_one(float4* slotBase, int x, int y,
                                          float fx, float fy, float w) {
    const float x2 = (float)x + fx;
    const float y2 = (float)y + fy;

    // Invalid pixels deposit exactly 0 in the reference -> skip.
    if (!(x2 >= 0.0f && x2 <= (float)(Wn - 1) &&
          y2 >= 0.0f && y2 <= (float)(Hn - 1)))
        return;

    const float vx = -fx * w;
    const float vy = -fy * w;

    // floor == trunc (non-negative by validity check)
    const int ixL = (int)x2;
    const int iyT = (int)y2;
    const int ixR = min(ixL + 1, Wn - 1);
    const int iyB = min(iyT + 1, Hn - 1);

    // lo half -> corner ixL, hi half -> corner ixR.
    // ixR==ixL (x2 == W-1 exactly): double lo payload, zero hi
    // (rn(2v) == 2*rn(v) in f16, bit-identical to two adds).
    const bool  dup = (ixR == ixL);
    const float m   = dup ? 2.0f : 1.0f;

    const unsigned r0 = h2_to_u32(__floats2half2_rn(vx * m, vy * m));
    const unsigned r1 = h2_to_u32(__floats2half2_rn(w * m, 0.0f));
    const unsigned r2 = dup ? 0u : h2_to_u32(__floats2half2_rn(vx, vy));
    const unsigned r3 = dup ? 0u : h2_to_u32(__floats2half2_rn(w, 0.0f));

    const int s  = ixL & 1;        // lattice parity
    const int kp = ixL >> 1;       // pair index

    float4* lat = slotBase + (size_t)s * LAT1 + kp;
    red_add_v4_f16x2(lat + iyT * WP, r0, r1, r2, r3);
    red_add_v4_f16x2(lat + iyB * WP, r0, r1, r2, r3);
}

__global__ void splat_kernel(const float* __restrict__ flow,
                             const float* __restrict__ depth, int slot) {
    const int t  = blockIdx.x * blockDim.x + threadIdx.x;   // [0, HW/2)
    const int p2 = t * 2;
    const int y  = p2 / Wn;
    const int x  = p2 - y * Wn;

    const float2 fx01 = *(const float2*)(flow + p2);
    const float2 fy01 = *(const float2*)(flow + HW + p2);
    const float2 d01  = *(const float2*)(depth + p2);

    float4* slotBase = g_lat + (size_t)slot * 2 * LAT1;
    splat_one(slotBase, x,     y, fx01.x, fy01.x, d01.x);
    splat_one(slotBase, x + 1, y, fx01.y, fy01.y, d01.y);
}

// ---------------------------------------------------------------------------
// Normalize body (4 pixels/thread, R12-proven). latS = slot base.
// ---------------------------------------------------------------------------
__device__ __forceinline__ void normalize_body(int t, const float4* latS,
                                               float* __restrict__ out, int gbase) {
    const int p4 = t * 4;
    const int y  = p4 / Wn;
    const int x0 = p4 - y * Wn;       // multiple of 4
    const int k  = x0 >> 1;           // even-lattice pair index (even)

    const size_t rowc = (size_t)y * WP;
    const uint4* latE = (const uint4*)latS;
    const uint2* latO = (const uint2*)(latS + (size_t)LAT1);   // 8B half-cells

    const uint4 e0 = latE[rowc + k];
    const uint4 e1 = latE[rowc + k + 1];

    float2 xyO0 = make_float2(0.f, 0.f);
    float  wO0  = 0.f;
    if (x0 > 0) {
        const uint2 oh = latO[((rowc + k - 1) << 1) | 1];   // odd pair k-1 hi
        xyO0 = __half22float2(u32_to_h2(oh.x));
        wO0  = __low2float(u32_to_h2(oh.y));
    }
    const uint4 om = latE[(size_t)LAT1 + rowc + k];          // odd pair k full
    const uint2 ol = latO[((rowc + k + 1) << 1)];            // odd pair k+1 lo

    float sxv[4], syv[4], cntv[4];
    {
        const float2 xyE = __half22float2(u32_to_h2(e0.x));
        const float  wE  = __low2float(u32_to_h2(e0.y));
        sxv[0] = xyE.x + xyO0.x; syv[0] = xyE.y + xyO0.y; cntv[0] = wE + wO0;
    }
    {
        const float2 xyE = __half22float2(u32_to_h2(e0.z));
        const float  wE  = __low2float(u32_to_h2(e0.w));
        const float2 xyO = __half22float2(u32_to_h2(om.x));
        const float  wO  = __low2float(u32_to_h2(om.y));
        sxv[1] = xyE.x + xyO.x; syv[1] = xyE.y + xyO.y; cntv[1] = wE + wO;
    }
    {
        const float2 xyE = __half22float2(u32_to_h2(e1.x));
        const float  wE  = __low2float(u32_to_h2(e1.y));
        const float2 xyO = __half22float2(u32_to_h2(om.z));
        const float  wO  = __low2float(u32_to_h2(om.w));
        sxv[2] = xyE.x + xyO.x; syv[2] = xyE.y + xyO.y; cntv[2] = wE + wO;
    }
    {
        const float2 xyE = __half22float2(u32_to_h2(e1.z));
        const float  wE  = __low2float(u32_to_h2(e1.w));
        const float2 xyO = __half22float2(u32_to_h2(ol.x));
        const float  wO  = __low2float(u32_to_h2(ol.y));
        sxv[3] = xyE.x + xyO.x; syv[3] = xyE.y + xyO.y; cntv[3] = wE + wO;
    }

    bool  h[4];
    float ox[4], oy[4];
    unsigned maskw = 0;
#pragma unroll
    for (int j = 0; j < 4; ++j) {
        h[j] = !(cntv[j] > 0.0f);
        const float inv = 1.0f / (h[j] ? 1.0f : cntv[j]);
        ox[j] = sxv[j] * inv;
        oy[j] = syv[j] * inv;
        maskw |= (h[j] ? 0u : 1u) << (j * 8);
    }

    *(float4*)(out + p4)      = make_float4(ox[0], ox[1], ox[2], ox[3]);
    *(float4*)(out + HW + p4) = make_float4(oy[0], oy[1], oy[2], oy[3]);
    *(unsigned*)(g_mask + gbase + p4) = maskw;

    const unsigned b0 = __ballot_sync(0xffffffffu, h[0]);
    const unsigned b1 = __ballot_sync(0xffffffffu, h[1]);
    const unsigned b2 = __ballot_sync(0xffffffffu, h[2]);
    const unsigned b3 = __ballot_sync(0xffffffffu, h[3]);
    const unsigned any = b0 | b1 | b2 | b3;
    if (any) {
        const int lane   = threadIdx.x & 31;
        const int leader = __ffs(any) - 1;
        const int total  = __popc(b0) + __popc(b1) + __popc(b2) + __popc(b3);
        int base = 0;
        if (lane == leader) base = atomicAdd(&g_hole_count, total);
        base = __shfl_sync(0xffffffffu, base, leader);
        const unsigned below = (1u << lane) - 1u;
        int off = base;
        if (h[0]) g_holes[off + __popc(b0 & below)] = gbase + p4;
        off += __popc(b0);
        if (h[1]) g_holes[off + __popc(b1 & below)] = gbase + p4 + 1;
        off += __popc(b1);
        if (h[2]) g_holes[off + __popc(b2 & below)] = gbase + p4 + 2;
        off += __popc(b2);
        if (h[3]) g_holes[off + __popc(b3 & below)] = gbase + p4 + 3;
    }
}

// ---------------------------------------------------------------------------
// Merged kernel: blocks [0, NORM_BLOCKS) normalize slice b-1 from slotNorm;
// blocks [NORM_BLOCKS, ...) zero slotZero for slice b+1. Slots differ.
// ---------------------------------------------------------------------------
__global__ void merged_kernel(float* __restrict__ outPrev, int gbasePrev,
                              int slotNorm, int slotZero) {
    if (blockIdx.x < NORM_BLOCKS) {
        normalize_body(blockIdx.x * blockDim.x + threadIdx.x,
                       g_lat + (size_t)slotNorm * 2 * LAT1, outPrev, gbasePrev);
    } else {
        const int i = (blockIdx.x - NORM_BLOCKS) * blockDim.x + threadIdx.x;
        g_lat[(size_t)slotZero * 2 * LAT1 + i] = make_float4(0.f, 0.f, 0.f, 0.f);
    }
}

// Normalize-only kernel (final slice drain).
__global__ void norm_kernel(float* __restrict__ out, int gbase, int slot) {
    normalize_body(blockIdx.x * blockDim.x + threadIdx.x,
                   g_lat + (size_t)slot * 2 * LAT1, out, gbase);
}

// ---------------------------------------------------------------------------
// Hole fill: LOCKSTEP 4-direction walk. The four directional chains are
// independent; stepping them together batches up to 4 mask loads into one
// memory round-trip instead of running 4 sequential dependent chains.
// Writes only holes, reads only filled pixels -> race-free in-place.
// ---------------------------------------------------------------------------
__global__ void fill_kernel(float* __restrict__ out) {
    const int n      = g_hole_count;
    const int stride = gridDim.x * blockDim.x;

    for (int j = blockIdx.x * blockDim.x + threadIdx.x; j < n; j += stride) {
        const int i = g_holes[j];
        const int b = i / HW;
        const int p = i - b * HW;
        const int y = p / Wn;
        const int x = p - y * Wn;

        const unsigned char* m  = g_mask + (size_t)b * HW;
        float*               o0 = out + (size_t)b * 2 * HW;
        float*               o1 = o0 + HW;
        const int row = y * Wn;

        float sx = 0.f, sy = 0.f;
        int   s  = 0;

        int  xl = x - 1, xr = x + 1, yu = y - 1, yd = y + 1;
        bool dl = (xl < 0), dr = (xr >= Wn), du = (yu < 0), dd = (yd >= Hn);

        while (!(dl && dr && du && dd)) {
            // Batched independent mask probes (compiler issues all 4 together).
            const unsigned char vl = dl ? 0 : m[row + xl];
            const unsigned char vr = dr ? 0 : m[row + xr];
            const unsigned char vu = du ? 0 : m[yu * Wn + x];
            const unsigned char vd = dd ? 0 : m[yd * Wn + x];

            if (!dl) {
                if (vl) { const int q = row + xl; sx += o0[q]; sy += o1[q]; s++; dl = true; }
                else    { --xl; dl = (xl < 0); }
            }
            if (!dr) {
                if (vr) { const int q = row + xr; sx += o0[q]; sy += o1[q]; s++; dr = true; }
                else    { ++xr; dr = (xr >= Wn); }
            }
            if (!du) {
                if (vu) { const int q = yu * Wn + x; sx += o0[q]; sy += o1[q]; s++; du = true; }
                else    { --yu; du = (yu < 0); }
            }
            if (!dd) {
                if (vd) { const int q = yd * Wn + x; sx += o0[q]; sy += o1[q]; s++; dd = true; }
                else    { ++yd; dd = (yd >= Hn); }
            }
        }

        if (s > 0) {
            const float inv = 1.0f / (float)s;
            o0[row + x] = sx * inv;
            o1[row + x] = sy * inv;
        }
        // s == 0: out already 0 at holes (count==0 implies acc.xy==0)
    }
}

// ---------------------------------------------------------------------------
// Launch: R13-proven ping-pong pipeline.
// ---------------------------------------------------------------------------
extern "C" void kernel_launch(void* const* d_in, const int* in_sizes, int n_in,
                              void* d_out, int out_size) {
    const float* flow  = (const float*)d_in[0];   // (B, 2, H, W) fp32
    const float* depth = (const float*)d_in[1];   // (B, 1, H, W) fp32
    float*       out   = (float*)d_out;           // (B, 2, H, W) fp32

    zero_kernel<<<ZERO_BLOCKS, 256>>>(0, 1);      // slot0 + reset hole counter

    for (int b = 0; b < Bn; ++b) {
        splat_kernel<<<4050, 256>>>(flow + (size_t)b * 2 * HW,
                                    depth + (size_t)b * HW, b & 1);
        if (b < Bn - 1) {
            merged_kernel<<<NORM_BLOCKS + ZERO_BLOCKS, 256>>>(
                out + (size_t)b * 2 * HW, b * HW, b & 1, (b + 1) & 1);
        }
    }
    norm_kernel<<<NORM_BLOCKS, 256>>>(out + (size_t)(Bn - 1) * 2 * HW,
                                      (Bn - 1) * HW, (Bn - 1) & 1);
    fill_kernel<<<2048, 256>>>(out);
}